// round 15
// baseline (speedup 1.0000x reference)
#include <cuda_runtime.h>
#include <cuda.h>
#include <math.h>

// Lowpass EMA scan: out[b,t,u] = (1-s[u])*x[b,t,u] + s[u]*prev
// R15 hybrid: champion cp.async input pipeline + TMA tensor STORES.
// Rationale: fine-grained interleaved STG.32 forces DRAM read/write bus
// turnarounds; one UTMASTG per 32KB tile gives the memory controller long
// contiguous write bursts. Input: 4-stage ring, 3 tiles ahead (96KB/SM,
// proven sufficient in R7). Output: 2 smem tiles, bulk_group pacing.

#define LP_B   16
#define LP_T   2048
#define LP_U   1024
#define TPB    128
#define TT     64
#define NIT    (LP_T / TT)        // 32
#define RING_IN 4
#define AHEAD   3
#define STAGE_FLOATS (TT * TPB)                   // 8192 floats = 32KB
#define TILE_BYTES   (STAGE_FLOATS * 4)
#define SMEM_BYTES   ((RING_IN + 2) * TILE_BYTES) // 192KB

__device__ __forceinline__ void cp_async16(float* smem_dst, const float* gsrc) {
    unsigned sdst = (unsigned)__cvta_generic_to_shared(smem_dst);
    asm volatile("cp.async.cg.shared.global [%0], [%1], 16;\n"
                 :: "r"(sdst), "l"(gsrc));
}
__device__ __forceinline__ void cp_async_commit() {
    asm volatile("cp.async.commit_group;\n" ::: "memory");
}
template <int N>
__device__ __forceinline__ void cp_async_wait() {
    asm volatile("cp.async.wait_group %0;\n" :: "n"(N) : "memory");
}
__device__ __forceinline__ void tma_store_2d(const CUtensorMap* tm, int cx, int cy,
                                             unsigned smem_src) {
    asm volatile(
        "cp.async.bulk.tensor.2d.global.shared::cta.tile.bulk_group "
        "[%0, {%1, %2}], [%3];"
        :: "l"(tm), "r"(cx), "r"(cy), "r"(smem_src) : "memory");
}
__device__ __forceinline__ void tma_store_commit() {
    asm volatile("cp.async.bulk.commit_group;" ::: "memory");
}
template <int N>
__device__ __forceinline__ void tma_store_wait() {
    asm volatile("cp.async.bulk.wait_group %0;" :: "n"(N) : "memory");
}

__global__ void __launch_bounds__(TPB, 1)
lowpass_hybrid_kernel(const float* __restrict__ x,
                      const float* __restrict__ level_var,
                      const float* __restrict__ smoothing_var,
                      const __grid_constant__ CUtensorMap otmap)
{
    extern __shared__ __align__(128) float xs[];          // [RING_IN][TT][TPB]
    float* outs = xs + RING_IN * STAGE_FLOATS;            // [2][TT][TPB]
    const unsigned outs_u = (unsigned)__cvta_generic_to_shared(outs);

    const int tid = threadIdx.x;
    const int b   = blockIdx.x >> 3;          // 0..15
    const int u0  = (blockIdx.x & 7) << 7;    // 0,128,...,896
    const int u   = u0 + tid;
    const int row0 = b * LP_T;

    const float sv = smoothing_var[u];
    const float s  = 1.0f / (1.0f + expf(-sv));
    const float c  = 1.0f - s;
    float level    = level_var[u];

    const float* __restrict__ xb = x + (size_t)b * LP_T * LP_U;

    if (tid == 0)
        asm volatile("prefetch.tensormap [%0];" :: "l"(&otmap));

    // Load mapping: row = 128 floats = 512B = 32 threads x 16B.
    const int lrow = tid >> 5;          // 0..3
    const int lcol = (tid & 31) << 2;   // 0,4,...,124

    // Prologue: input tiles 0..2 in flight (3 groups)
#pragma unroll
    for (int p = 0; p < AHEAD; p++) {
        float* st = xs + p * STAGE_FLOATS;
#pragma unroll
        for (int k = 0; k < 16; k++) {
            const int r = lrow + 4 * k;
            cp_async16(st + r * TPB + lcol,
                       xb + (size_t)(p * TT + r) * LP_U + u0 + lcol);
        }
        cp_async_commit();
    }

    for (int it = 0; it < NIT; it++) {
        // Issue input tile it+AHEAD (slot held tile it-1, consumed last iter
        // and fenced by last iter's barriers).
        const int ls = it + AHEAD;
        if (ls < NIT) {
            float* st = xs + (ls % RING_IN) * STAGE_FLOATS;
#pragma unroll
            for (int k = 0; k < 16; k++) {
                const int r = lrow + 4 * k;
                cp_async16(st + r * TPB + lcol,
                           xb + (size_t)(ls * TT + r) * LP_U + u0 + lcol);
            }
        }
        cp_async_commit();          // uniform group count

        cp_async_wait<AHEAD>();     // input tile 'it' landed (this thread)
        if (tid == 0)
            tma_store_wait<1>();    // out slot it%2 drained (store it-2 done)
        __syncthreads();            // tile visible to all; out slot reusable

        // Consume: register carry; results go to smem out tile (STS)
        const float* tile = xs + (it % RING_IN) * STAGE_FLOATS;
        float* otile = outs + (it & 1) * STAGE_FLOATS;
#pragma unroll
        for (int t = 0; t < TT; t++) {
            level = fmaf(s, level, c * tile[t * TPB + tid]);
            otile[t * TPB + tid] = level;
        }

        asm volatile("fence.proxy.async.shared::cta;" ::: "memory");
        __syncthreads();            // all STS visible to async proxy

        if (tid == 0) {
            tma_store_2d(&otmap, u0, row0 + it * TT,
                         outs_u + (unsigned)((it & 1) * TILE_BYTES));
            tma_store_commit();
        }
    }

    if (tid == 0)
        tma_store_wait<0>();        // stores complete before smem is freed
    __syncthreads();
}

// Host-side tensormap (driver entry point via cudart; no -lcuda)
typedef CUresult (*EncodeTiledFn)(
    CUtensorMap*, CUtensorMapDataType, cuuint32_t, void*,
    const cuuint64_t*, const cuuint64_t*, const cuuint32_t*, const cuuint32_t*,
    CUtensorMapInterleave, CUtensorMapSwizzle, CUtensorMapL2promotion,
    CUtensorMapFloatOOBfill);

extern "C" void kernel_launch(void* const* d_in, const int* in_sizes, int n_in,
                              void* d_out, int out_size)
{
    const float* x         = (const float*)d_in[0];  // [B,T,U]
    const float* level_var = (const float*)d_in[1];  // [1,U]
    const float* smoothing = (const float*)d_in[2];  // [1,U]
    float* out             = (float*)d_out;          // [B,T,U]

    static EncodeTiledFn encode_fn = nullptr;
    static CUtensorMap otmap;
    static const void* cached_out = nullptr;
    static int smem_set = 0;

    if (!smem_set) {
        cudaFuncSetAttribute(lowpass_hybrid_kernel,
                             cudaFuncAttributeMaxDynamicSharedMemorySize,
                             SMEM_BYTES);
        smem_set = 1;
    }

    if (cached_out != (const void*)out) {
        if (!encode_fn) {
            void* fp = nullptr;
            cudaGetDriverEntryPoint("cuTensorMapEncodeTiled", &fp,
                                    cudaEnableDefault);
            encode_fn = (EncodeTiledFn)fp;
        }
        // 2D: dim0 = U floats (contiguous), dim1 = B*T rows; box 128 x 64
        cuuint64_t gdim[2]    = { (cuuint64_t)LP_U, (cuuint64_t)(LP_B * LP_T) };
        cuuint64_t gstride[1] = { (cuuint64_t)LP_U * sizeof(float) };
        cuuint32_t box[2]     = { (cuuint32_t)TPB, (cuuint32_t)TT };
        cuuint32_t estr[2]    = { 1, 1 };
        encode_fn(&otmap, CU_TENSOR_MAP_DATA_TYPE_FLOAT32, 2, (void*)out,
                  gdim, gstride, box, estr,
                  CU_TENSOR_MAP_INTERLEAVE_NONE, CU_TENSOR_MAP_SWIZZLE_NONE,
                  CU_TENSOR_MAP_L2_PROMOTION_L2_128B,
                  CU_TENSOR_MAP_FLOAT_OOB_FILL_NONE);
        cached_out = (const void*)out;
    }

    const int blocks = LP_B * (LP_U / TPB);          // 128
    lowpass_hybrid_kernel<<<blocks, TPB, SMEM_BYTES>>>(x, level_var, smoothing, otmap);
}

// round 16
// speedup vs baseline: 1.4052x; 1.4052x over previous
#include <cuda_runtime.h>
#include <cuda_bf16.h>
#include <math.h>

// Lowpass EMA scan: out[b,t,u] = (1-s[u])*x[b,t,u] + s[u]*prev
// FINAL CHAMPION (R8 config, best measured 47.1us):
// thread-per-chain register carry + cp.async-staged input tiles.
// 6-stage ring, 4-tile prologue, next-tile issue hoisted above the wait
// -> ~5 tiles (160KB/SM) of reads in flight.
// Converged at the mixed R/W HBM ceiling (~5.7 TB/s) — depth, quantum,
// SM coverage, carry-chain, TMA loads, and TMA stores all proven
// non-binding or negative in R6-R15.
//
// Block = 128 threads = chains (b, u0..u0+127); grid = 128 blocks.
// Tile = 64 t-rows x 512B (32KB). Loads: 16B cp.async.cg, coalesced.

#define LP_B   16
#define LP_T   2048
#define LP_U   1024
#define TPB    128           // threads = chains per block
#define TT     64            // t per tile
#define NIT    (LP_T / TT)   // 32
#define RING   6
#define STAGE_FLOATS (TT * TPB)                 // 8192 floats = 32KB
#define SMEM_BYTES   (RING * STAGE_FLOATS * 4)  // 192KB

__device__ __forceinline__ void cp_async16(float* smem_dst, const float* gsrc) {
    unsigned sdst = (unsigned)__cvta_generic_to_shared(smem_dst);
    asm volatile("cp.async.cg.shared.global [%0], [%1], 16;\n"
                 :: "r"(sdst), "l"(gsrc));
}
__device__ __forceinline__ void cp_async_commit() {
    asm volatile("cp.async.commit_group;\n" ::: "memory");
}
template <int N>
__device__ __forceinline__ void cp_async_wait() {
    asm volatile("cp.async.wait_group %0;\n" :: "n"(N) : "memory");
}

__global__ void __launch_bounds__(TPB, 1)
lowpass_cpasync_kernel(const float* __restrict__ x,
                       const float* __restrict__ level_var,
                       const float* __restrict__ smoothing_var,
                       float* __restrict__ out)
{
    extern __shared__ float xs[];   // [RING][TT][TPB]

    const int tid = threadIdx.x;
    const int b   = blockIdx.x >> 3;          // 0..15
    const int u0  = (blockIdx.x & 7) << 7;    // 0,128,...,896
    const int u   = u0 + tid;

    const float sv = smoothing_var[u];
    const float s  = 1.0f / (1.0f + expf(-sv));
    const float c  = 1.0f - s;
    float level    = level_var[u];

    const float* __restrict__ xb = x   + (size_t)b * LP_T * LP_U;
    float*       __restrict__ ob = out + (size_t)b * LP_T * LP_U;

    // Load mapping: thread covers rows (tid>>5)+4k, 16B at float col (tid&31)*4
    const int lrow = tid >> 5;          // 0..3
    const int lcol = (tid & 31) << 2;   // 0,4,...,124

    // Prologue: tiles 0..3 in flight (4 groups)
#pragma unroll
    for (int p = 0; p < 4; p++) {
        float* st = xs + p * STAGE_FLOATS;
#pragma unroll
        for (int k = 0; k < 16; k++) {
            const int r = lrow + 4 * k;
            cp_async16(st + r * TPB + lcol,
                       xb + (size_t)(p * TT + r) * LP_U + u0 + lcol);
        }
        cp_async_commit();
    }

    for (int it = 0; it < NIT; it++) {
        // Issue tile it+4 FIRST (slot (it+4)%RING held tile it-2, whose
        // consumption by all warps is fenced by the barrier at it-1).
        const int ls = it + 4;
        if (ls < NIT) {
            float* st = xs + (ls % RING) * STAGE_FLOATS;
#pragma unroll
            for (int k = 0; k < 16; k++) {
                const int r = lrow + 4 * k;
                cp_async16(st + r * TPB + lcol,
                           xb + (size_t)(ls * TT + r) * LP_U + u0 + lcol);
            }
        }
        cp_async_commit();      // empty groups near the end keep counts uniform

        cp_async_wait<4>();     // <=4 of 5 pending -> tile 'it' has landed
        __syncthreads();        // all threads' slices visible; old slot free

        // Consume tile it: serial carry, coalesced streaming stores
        const float* tile = xs + (it % RING) * STAGE_FLOATS;
        float* op = ob + (size_t)(it * TT) * LP_U + u;
#pragma unroll
        for (int t = 0; t < TT; t++) {
            level = fmaf(s, level, c * tile[t * TPB + tid]);
            __stcs(op + (size_t)t * LP_U, level);
        }
    }
}

extern "C" void kernel_launch(void* const* d_in, const int* in_sizes, int n_in,
                              void* d_out, int out_size)
{
    const float* x         = (const float*)d_in[0];  // [B,T,U]
    const float* level_var = (const float*)d_in[1];  // [1,U]
    const float* smoothing = (const float*)d_in[2];  // [1,U]
    float* out             = (float*)d_out;          // [B,T,U]

    static int smem_set = 0;
    if (!smem_set) {
        cudaFuncSetAttribute(lowpass_cpasync_kernel,
                             cudaFuncAttributeMaxDynamicSharedMemorySize,
                             SMEM_BYTES);
        smem_set = 1;
    }

    const int blocks = LP_B * (LP_U / TPB);          // 128
    lowpass_cpasync_kernel<<<blocks, TPB, SMEM_BYTES>>>(x, level_var, smoothing, out);
}

// round 17
// speedup vs baseline: 1.4465x; 1.0294x over previous
#include <cuda_runtime.h>
#include <cuda_bf16.h>
#include <math.h>

// Lowpass EMA scan: out[b,t,u] = (1-s[u])*x[b,t,u] + s[u]*prev
// R17: warp-DECOUPLED pipelines. Each warp owns 32 chains + a private
// 6-slot cp.async ring (48KB). No __syncthreads in the mainloop: cp.async
// group tracking is per-thread, so issue->commit->wait_group->__syncwarp
// runs independently per warp. Removes the per-tile block-wide lockstep
// that made every warp pay the slowest warp's memory tail 32x per block.
// Geometry/traffic identical to champion: 128 blocks x 128 threads,
// 16B cp.async.cg loads, 128B/warp coalesced __stcs stores.

#define LP_B   16
#define LP_T   2048
#define LP_U   1024
#define TPB    128
#define WPB    4             // warps per block
#define TT     64            // t per tile
#define NIT    (LP_T / TT)   // 32
#define RING   6
#define AHEAD  4
#define WARP_TILE_FLOATS (TT * 32)                       // 2048 floats = 8KB
#define WARP_RING_FLOATS (RING * WARP_TILE_FLOATS)       // 48KB / warp
#define SMEM_BYTES       (WPB * WARP_RING_FLOATS * 4)    // 192KB

__device__ __forceinline__ void cp_async16(float* smem_dst, const float* gsrc) {
    unsigned sdst = (unsigned)__cvta_generic_to_shared(smem_dst);
    asm volatile("cp.async.cg.shared.global [%0], [%1], 16;\n"
                 :: "r"(sdst), "l"(gsrc));
}
__device__ __forceinline__ void cp_async_commit() {
    asm volatile("cp.async.commit_group;\n" ::: "memory");
}
template <int N>
__device__ __forceinline__ void cp_async_wait() {
    asm volatile("cp.async.wait_group %0;\n" :: "n"(N) : "memory");
}

__global__ void __launch_bounds__(TPB, 1)
lowpass_warpdec_kernel(const float* __restrict__ x,
                       const float* __restrict__ level_var,
                       const float* __restrict__ smoothing_var,
                       float* __restrict__ out)
{
    extern __shared__ float xs[];   // [WPB][RING][TT][32]

    const int tid  = threadIdx.x;
    const int w    = tid >> 5;               // warp 0..3
    const int lane = tid & 31;
    const int b    = blockIdx.x >> 3;        // 0..15
    const int u0w  = ((blockIdx.x & 7) << 7) + (w << 5);  // this warp's u base
    const int u    = u0w + lane;

    const float sv = smoothing_var[u];
    const float s  = 1.0f / (1.0f + expf(-sv));
    const float c  = 1.0f - s;
    float level    = level_var[u];

    const float* __restrict__ xb = x   + (size_t)b * LP_T * LP_U;
    float*       __restrict__ ob = out + (size_t)b * LP_T * LP_U;

    float* wring = xs + w * WARP_RING_FLOATS;

    // Load mapping: row = 32 floats = 128B = 8 lanes x 16B.
    // 32 lanes cover 4 rows per step; 16 steps cover the 64-row tile.
    const int lrow = lane >> 3;          // 0..3
    const int lcol = (lane & 7) << 2;    // 0,4,...,28 (float index in row)

    // Prologue: tiles 0..AHEAD-1 in flight (per-warp groups)
#pragma unroll
    for (int p = 0; p < AHEAD; p++) {
        float* st = wring + p * WARP_TILE_FLOATS;
#pragma unroll
        for (int k = 0; k < 16; k++) {
            const int r = lrow + 4 * k;
            cp_async16(st + r * 32 + lcol,
                       xb + (size_t)(p * TT + r) * LP_U + u0w + lcol);
        }
        cp_async_commit();
    }

    for (int it = 0; it < NIT; it++) {
        // Issue tile it+AHEAD first (slot held tile it-2: consumed two
        // iterations ago by THIS warp; __syncwarp then ordered all lanes).
        const int ls = it + AHEAD;
        if (ls < NIT) {
            float* st = wring + (ls % RING) * WARP_TILE_FLOATS;
#pragma unroll
            for (int k = 0; k < 16; k++) {
                const int r = lrow + 4 * k;
                cp_async16(st + r * 32 + lcol,
                           xb + (size_t)(ls * TT + r) * LP_U + u0w + lcol);
            }
        }
        cp_async_commit();       // uniform group count per thread

        cp_async_wait<AHEAD>();  // tile 'it' landed (this thread's groups)
        __syncwarp();            // cross-lane visibility within the warp

        // Consume tile it: serial carry, 128B/warp coalesced stores
        const float* tile = wring + (it % RING) * WARP_TILE_FLOATS;
        float* op = ob + (size_t)(it * TT) * LP_U + u;
#pragma unroll
        for (int t = 0; t < TT; t++) {
            level = fmaf(s, level, c * tile[t * 32 + lane]);
            __stcs(op + (size_t)t * LP_U, level);
        }
        __syncwarp();            // all lanes done with slot before its reuse
    }
}

extern "C" void kernel_launch(void* const* d_in, const int* in_sizes, int n_in,
                              void* d_out, int out_size)
{
    const float* x         = (const float*)d_in[0];  // [B,T,U]
    const float* level_var = (const float*)d_in[1];  // [1,U]
    const float* smoothing = (const float*)d_in[2];  // [1,U]
    float* out             = (float*)d_out;          // [B,T,U]

    static int smem_set = 0;
    if (!smem_set) {
        cudaFuncSetAttribute(lowpass_warpdec_kernel,
                             cudaFuncAttributeMaxDynamicSharedMemorySize,
                             SMEM_BYTES);
        smem_set = 1;
    }

    const int blocks = LP_B * (LP_U / TPB);          // 128
    lowpass_warpdec_kernel<<<blocks, TPB, SMEM_BYTES>>>(x, level_var, smoothing, out);
}